// round 4
// baseline (speedup 1.0000x reference)
#include <cuda_runtime.h>

// out[v] = sum over edges (u->v) of emb[u].  D_FEAT = 64 fp32.
// Strategy: build CSR-by-dst inside the graph (histogram -> scan -> scatter),
// then pull-mode sum per node with NO float atomics.
//  k1: zero degree counters
//  k2: histogram of dst
//  k3: single-block exclusive scan (50K elements, 1024 threads)
//  k4: scatter src ids into dst-ordered permutation array
//  k5: per-node gather-sum (16 threads/node, one float4 chunk each)

#define N_NODES_MAX 50000
#define N_EDGES_MAX 1250000
#define D_FEAT 64
#define VEC_PER_ROW 16  // 64 floats / 4

__device__ int g_deg[N_NODES_MAX];
__device__ int g_off[N_NODES_MAX + 1];
__device__ int g_pos[N_NODES_MAX];
__device__ int g_perm[N_EDGES_MAX];

__global__ void zero_deg_kernel(int n_nodes) {
    int i = blockIdx.x * blockDim.x + threadIdx.x;
    if (i < n_nodes) g_deg[i] = 0;
}

__global__ void hist_kernel(const int* __restrict__ dst, int n_edges) {
    int i = blockIdx.x * blockDim.x + threadIdx.x;
    if (i < n_edges) atomicAdd(&g_deg[dst[i]], 1);
}

__global__ void scan_kernel(int n_nodes) {
    const int T = 1024;
    int tid = threadIdx.x;
    int chunk = (n_nodes + T - 1) / T;
    int base = tid * chunk;

    int sum = 0;
    for (int i = 0; i < chunk; i++) {
        int idx = base + i;
        if (idx < n_nodes) sum += g_deg[idx];
    }

    __shared__ int s[T];
    s[tid] = sum;
    __syncthreads();
    for (int off = 1; off < T; off <<= 1) {
        int v = (tid >= off) ? s[tid - off] : 0;
        __syncthreads();
        s[tid] += v;
        __syncthreads();
    }
    int run = s[tid] - sum;  // exclusive prefix for this thread's chunk

    for (int i = 0; i < chunk; i++) {
        int idx = base + i;
        if (idx < n_nodes) {
            g_off[idx] = run;
            g_pos[idx] = run;
            run += g_deg[idx];
        }
    }
    if (tid == T - 1) g_off[n_nodes] = s[T - 1];
}

__global__ void scatter_kernel(const int* __restrict__ src,
                               const int* __restrict__ dst, int n_edges) {
    int i = blockIdx.x * blockDim.x + threadIdx.x;
    if (i < n_edges) {
        int p = atomicAdd(&g_pos[dst[i]], 1);
        g_perm[p] = src[i];
    }
}

// 16 threads per node; thread owns one float4 (16B) column chunk.
// 4 independent accumulators -> 4 independent load+FMA chains (MLP).
__global__ void node_sum_kernel(const float4* __restrict__ emb,
                                float4* __restrict__ out, int n_nodes) {
    int t = blockIdx.x * blockDim.x + threadIdx.x;
    int node = t >> 4;
    int c = t & 15;
    if (node >= n_nodes) return;

    int beg = g_off[node];
    int end = g_off[node + 1];

    float4 acc0 = make_float4(0.f, 0.f, 0.f, 0.f);
    float4 acc1 = make_float4(0.f, 0.f, 0.f, 0.f);
    float4 acc2 = make_float4(0.f, 0.f, 0.f, 0.f);
    float4 acc3 = make_float4(0.f, 0.f, 0.f, 0.f);

    int j = beg;
    for (; j + 4 <= end; j += 4) {
        int s0 = g_perm[j + 0];
        int s1 = g_perm[j + 1];
        int s2 = g_perm[j + 2];
        int s3 = g_perm[j + 3];
        float4 a = __ldg(&emb[s0 * VEC_PER_ROW + c]);
        float4 b = __ldg(&emb[s1 * VEC_PER_ROW + c]);
        float4 d = __ldg(&emb[s2 * VEC_PER_ROW + c]);
        float4 e = __ldg(&emb[s3 * VEC_PER_ROW + c]);
        acc0.x += a.x; acc0.y += a.y; acc0.z += a.z; acc0.w += a.w;
        acc1.x += b.x; acc1.y += b.y; acc1.z += b.z; acc1.w += b.w;
        acc2.x += d.x; acc2.y += d.y; acc2.z += d.z; acc2.w += d.w;
        acc3.x += e.x; acc3.y += e.y; acc3.z += e.z; acc3.w += e.w;
    }
    for (; j < end; j++) {
        float4 a = __ldg(&emb[g_perm[j] * VEC_PER_ROW + c]);
        acc0.x += a.x; acc0.y += a.y; acc0.z += a.z; acc0.w += a.w;
    }

    float4 r;
    r.x = (acc0.x + acc1.x) + (acc2.x + acc3.x);
    r.y = (acc0.y + acc1.y) + (acc2.y + acc3.y);
    r.z = (acc0.z + acc1.z) + (acc2.z + acc3.z);
    r.w = (acc0.w + acc1.w) + (acc2.w + acc3.w);
    out[node * VEC_PER_ROW + c] = r;
}

extern "C" void kernel_launch(void* const* d_in, const int* in_sizes, int n_in,
                              void* d_out, int out_size) {
    const float4* emb = (const float4*)d_in[0];
    const int*    src = (const int*)d_in[1];
    const int*    dst = (const int*)d_in[2];

    int n_edges = in_sizes[1];
    int n_nodes = out_size / D_FEAT;

    int eb = (n_edges + 255) / 256;
    int nb = (n_nodes + 255) / 256;

    zero_deg_kernel<<<nb, 256>>>(n_nodes);
    hist_kernel<<<eb, 256>>>(dst, n_edges);
    scan_kernel<<<1, 1024>>>(n_nodes);
    scatter_kernel<<<eb, 256>>>(src, dst, n_edges);

    int tot = n_nodes * 16;
    node_sum_kernel<<<(tot + 255) / 256, 256>>>(emb, (float4*)d_out, n_nodes);
}

// round 5
// speedup vs baseline: 2.2608x; 2.2608x over previous
#include <cuda_runtime.h>

// out[v] = sum over edges (u->v) of emb[u], D_FEAT = 64 fp32.
// Edge-parallel atomic scatter with per-thread MLP=4:
// 16 threads form a group owning one EDGE QUAD (4 consecutive edges).
// Each thread handles one float4 chunk (16B) of the 256B feature row for
// all 4 edges: broadcast int4 index loads, 4 independent gathers (overlap
// the ~240cyc L2 latency), 4 vector no-return reductions.

#define D_FEAT 64
#define VEC_PER_ROW 16  // 64 floats / 4

__global__ void edge_scatter_sum4_kernel(const float4* __restrict__ emb,
                                         const int* __restrict__ src,
                                         const int* __restrict__ dst,
                                         float* __restrict__ out,
                                         int n_edges) {
    long long t = (long long)blockIdx.x * blockDim.x + threadIdx.x;
    int q = (int)(t >> 4);     // edge-quad index
    int c = (int)(t & 15);     // float4 chunk within the row
    int e0 = q * 4;
    if (e0 >= n_edges) return;

    if (e0 + 3 < n_edges) {
        // Vector path: one 16B load per index array (broadcast within group).
        int4 s = __ldg((const int4*)(src + e0));
        int4 d = __ldg((const int4*)(dst + e0));

        float4 v0 = __ldg(&emb[(long long)s.x * VEC_PER_ROW + c]);
        float4 v1 = __ldg(&emb[(long long)s.y * VEC_PER_ROW + c]);
        float4 v2 = __ldg(&emb[(long long)s.z * VEC_PER_ROW + c]);
        float4 v3 = __ldg(&emb[(long long)s.w * VEC_PER_ROW + c]);

        float* p0 = out + ((long long)d.x * D_FEAT + c * 4);
        float* p1 = out + ((long long)d.y * D_FEAT + c * 4);
        float* p2 = out + ((long long)d.z * D_FEAT + c * 4);
        float* p3 = out + ((long long)d.w * D_FEAT + c * 4);

        asm volatile("red.global.add.v4.f32 [%0], {%1, %2, %3, %4};"
                     :: "l"(p0), "f"(v0.x), "f"(v0.y), "f"(v0.z), "f"(v0.w) : "memory");
        asm volatile("red.global.add.v4.f32 [%0], {%1, %2, %3, %4};"
                     :: "l"(p1), "f"(v1.x), "f"(v1.y), "f"(v1.z), "f"(v1.w) : "memory");
        asm volatile("red.global.add.v4.f32 [%0], {%1, %2, %3, %4};"
                     :: "l"(p2), "f"(v2.x), "f"(v2.y), "f"(v2.z), "f"(v2.w) : "memory");
        asm volatile("red.global.add.v4.f32 [%0], {%1, %2, %3, %4};"
                     :: "l"(p3), "f"(v3.x), "f"(v3.y), "f"(v3.z), "f"(v3.w) : "memory");
    } else {
        // Tail: scalar index loads with per-edge predication.
        for (int e = e0; e < n_edges; e++) {
            int s = src[e];
            int d = dst[e];
            float4 v = __ldg(&emb[(long long)s * VEC_PER_ROW + c]);
            float* p = out + ((long long)d * D_FEAT + c * 4);
            asm volatile("red.global.add.v4.f32 [%0], {%1, %2, %3, %4};"
                         :: "l"(p), "f"(v.x), "f"(v.y), "f"(v.z), "f"(v.w) : "memory");
        }
    }
}

extern "C" void kernel_launch(void* const* d_in, const int* in_sizes, int n_in,
                              void* d_out, int out_size) {
    const float4* emb = (const float4*)d_in[0];
    const int*    src = (const int*)d_in[1];
    const int*    dst = (const int*)d_in[2];
    float* out = (float*)d_out;

    int n_edges = in_sizes[1];

    // Zero the poisoned output (async memset is graph-capturable).
    cudaMemsetAsync(d_out, 0, (size_t)out_size * sizeof(float));

    int n_quads = (n_edges + 3) / 4;
    long long total_threads = (long long)n_quads * 16;
    int block = 256;
    int grid = (int)((total_threads + block - 1) / block);
    edge_scatter_sum4_kernel<<<grid, block>>>(emb, src, dst, out, n_edges);
}